// round 9
// baseline (speedup 1.0000x reference)
#include <cuda_runtime.h>
#include <cuda_bf16.h>
#include <cstdint>
#include <cstddef>
#include <mma.h>

using namespace nvcuda;

#define B_ 8
#define S_ 2048
#define E_ 1024
#define QMAX 32512.0f   // |q| <= 32512 so qh=(q+128)>>8 fits int8

// ================= scratch (device globals; allocation-free rule) =================
__device__ float g_scales[8];                 // 0:Q 1:K 2:V 3:W 4:attn (absmax values)
__device__ float g_rowscale[(size_t)B_ * S_]; // per-row dequant step for P
__device__ char  c_Qhi[(size_t)B_ * S_ * E_]; // also reused for attn planes
__device__ char  c_Qlo[(size_t)B_ * S_ * E_];
__device__ char  c_Khi[(size_t)B_ * S_ * E_];
__device__ char  c_Klo[(size_t)B_ * S_ * E_];
__device__ char  c_Vthi[(size_t)B_ * E_ * S_];  // V transposed: [B, E, S]
__device__ char  c_Vtlo[(size_t)B_ * E_ * S_];
__device__ char  c_Whi[(size_t)E_ * E_];
__device__ char  c_Wlo[(size_t)E_ * E_];
__device__ char  c_Phi[(size_t)B_ * S_ * S_];
__device__ char  c_Plo[(size_t)B_ * S_ * S_];
__device__ float g_scores[(size_t)B_ * S_ * S_]; // scores f32; later reused as attn f32

// ================= helpers =================
__device__ __forceinline__ void cp16(uint32_t dst, const void* src) {
    asm volatile("cp.async.cg.shared.global [%0], [%1], 16;" :: "r"(dst), "l"(src) : "memory");
}
__device__ __forceinline__ uint32_t smem_u32(const void* p) {
    uint32_t a;
    asm("{ .reg .u64 t; cvta.to.shared.u64 t, %1; cvt.u32.u64 %0, t; }" : "=r"(a) : "l"(p));
    return a;
}
__device__ __forceinline__ void cp_commit() { asm volatile("cp.async.commit_group;" ::: "memory"); }
__device__ __forceinline__ void cp_wait1()  { asm volatile("cp.async.wait_group 1;" ::: "memory"); }

__device__ __forceinline__ void split_q(float x, float inv, char& qh, char& ql) {
    int q = __float2int_rn(x * inv);         // |q| <= 32512
    int h = (q + 128) >> 8;                  // [-127,127]
    qh = (char)h;
    ql = (char)(q - (h << 8));               // [-128,127]
}

// ================= scale init + absmax =================
__global__ void zero_scales_kernel() {
    if (threadIdx.x < 8) g_scales[threadIdx.x] = 0.f;
}

__global__ void absmax_kernel(const float4* __restrict__ x, int n4, int slot) {
    __shared__ float sm[8];
    float m = 0.f;
    for (int i = blockIdx.x * blockDim.x + threadIdx.x; i < n4; i += gridDim.x * blockDim.x) {
        float4 v = x[i];
        m = fmaxf(m, fmaxf(fmaxf(fabsf(v.x), fabsf(v.y)), fmaxf(fabsf(v.z), fabsf(v.w))));
    }
#pragma unroll
    for (int o = 16; o; o >>= 1) m = fmaxf(m, __shfl_xor_sync(0xffffffffu, m, o));
    int lane = threadIdx.x & 31, warp = threadIdx.x >> 5;
    if (lane == 0) sm[warp] = m;
    __syncthreads();
    if (threadIdx.x == 0) {
        float mm = sm[0];
#pragma unroll
        for (int w = 1; w < 8; w++) mm = fmaxf(mm, sm[w]);
        atomicMax(reinterpret_cast<int*>(&g_scales[slot]), __float_as_int(mm));
    }
}

// ================= quantize f32 -> int8 hi/lo planes (per-tensor scale) ==========
__global__ void __launch_bounds__(256) quant_plane(const float* __restrict__ x,
                                                   char* __restrict__ qh,
                                                   char* __restrict__ ql,
                                                   int n8, int slot) {
    int i = blockIdx.x * blockDim.x + threadIdx.x;
    if (i >= n8) return;
    float inv = QMAX / fmaxf(g_scales[slot], 1e-30f);
    const float4* x4 = reinterpret_cast<const float4*>(x) + (size_t)i * 2;
    float4 a = x4[0], b = x4[1];
    float f[8] = {a.x, a.y, a.z, a.w, b.x, b.y, b.z, b.w};
    char h[8], l[8];
#pragma unroll
    for (int j = 0; j < 8; j++) split_q(f[j], inv, h[j], l[j]);
    *reinterpret_cast<uint2*>(qh + (size_t)i * 8) = *reinterpret_cast<const uint2*>(h);
    *reinterpret_cast<uint2*>(ql + (size_t)i * 8) = *reinterpret_cast<const uint2*>(l);
}

// V [B,S,E] f32 -> transposed int8 planes [B,E,S] (per-tensor scale slot 2)
__global__ void __launch_bounds__(256) quantT_v(const float* __restrict__ v,
                                                char* __restrict__ hi,
                                                char* __restrict__ lo) {
    __shared__ float tile[32][33];
    int b = blockIdx.z;
    int s0 = blockIdx.x * 32, e0 = blockIdx.y * 32;
    int tx = threadIdx.x & 31, ty = threadIdx.x >> 5;
    float inv = QMAX / fmaxf(g_scales[2], 1e-30f);
    const float* vb = v + (size_t)b * S_ * E_;
#pragma unroll
    for (int k = 0; k < 4; k++)
        tile[ty + 8 * k][tx] = vb[(size_t)(s0 + ty + 8 * k) * E_ + e0 + tx];
    __syncthreads();
    char* hb = hi + (size_t)b * E_ * S_;
    char* lb = lo + (size_t)b * E_ * S_;
#pragma unroll
    for (int k = 0; k < 4; k++) {
        char h, l;
        split_q(tile[tx][ty + 8 * k], inv, h, l);
        size_t o = (size_t)(e0 + ty + 8 * k) * S_ + s0 + tx;
        hb[o] = h;
        lb[o] = l;
    }
}

// ================= softmax * mask -> int8 planes + per-row scale ================
__global__ void __launch_bounds__(256) softmax_quant_kernel(
    const float* __restrict__ scores, const float* __restrict__ mask,
    char* __restrict__ phi, char* __restrict__ plo, const int* __restrict__ sc) {
    __shared__ float redA[8], redB[8], redC[8];
    size_t row = blockIdx.x;
    const float4* srow = reinterpret_cast<const float4*>(scores + row * (size_t)S_);
    const float4* mrow = reinterpret_cast<const float4*>(mask + row * (size_t)S_);
    int t = threadIdx.x, lane = t & 31, warp = t >> 5;

    int iv = *sc;
    float denom = (iv == 32) ? 32.0f : __int_as_float(iv);
    float scale = 1.0f / denom;

    float v[8];
#pragma unroll
    for (int j = 0; j < 2; j++) {
        float4 x = srow[t + 256 * j];
        v[4 * j + 0] = x.x * scale; v[4 * j + 1] = x.y * scale;
        v[4 * j + 2] = x.z * scale; v[4 * j + 3] = x.w * scale;
    }
    float m = v[0];
#pragma unroll
    for (int j = 1; j < 8; j++) m = fmaxf(m, v[j]);
#pragma unroll
    for (int o = 16; o; o >>= 1) m = fmaxf(m, __shfl_xor_sync(0xffffffffu, m, o));
    if (lane == 0) redA[warp] = m;
    __syncthreads();
    float bm = redA[0];
#pragma unroll
    for (int w = 1; w < 8; w++) bm = fmaxf(bm, redA[w]);

    float e[8], s = 0.f;
#pragma unroll
    for (int j = 0; j < 8; j++) { e[j] = __expf(v[j] - bm); s += e[j]; }
#pragma unroll
    for (int o = 16; o; o >>= 1) s += __shfl_xor_sync(0xffffffffu, s, o);
    if (lane == 0) redB[warp] = s;
    __syncthreads();
    float bs = 0.f;
#pragma unroll
    for (int w = 0; w < 8; w++) bs += redB[w];
    float invs = 1.0f / bs;

    // p = prob * mask, find row max of p
    float p[8];
#pragma unroll
    for (int j = 0; j < 2; j++) {
        float4 mk = mrow[t + 256 * j];
        p[4 * j + 0] = e[4 * j + 0] * invs * mk.x;
        p[4 * j + 1] = e[4 * j + 1] * invs * mk.y;
        p[4 * j + 2] = e[4 * j + 2] * invs * mk.z;
        p[4 * j + 3] = e[4 * j + 3] * invs * mk.w;
    }
    float pm = p[0];
#pragma unroll
    for (int j = 1; j < 8; j++) pm = fmaxf(pm, p[j]);
#pragma unroll
    for (int o = 16; o; o >>= 1) pm = fmaxf(pm, __shfl_xor_sync(0xffffffffu, pm, o));
    if (lane == 0) redC[warp] = pm;
    __syncthreads();
    float bpm = redC[0];
#pragma unroll
    for (int w = 1; w < 8; w++) bpm = fmaxf(bpm, redC[w]);
    bpm = fmaxf(bpm, 1e-30f);
    if (t == 0) g_rowscale[row] = bpm / QMAX;   // true dequant step for this row
    float inv2 = QMAX / bpm;

    char* ph = phi + row * (size_t)S_;
    char* pl = plo + row * (size_t)S_;
#pragma unroll
    for (int j = 0; j < 2; j++) {
        char h[4], l[4];
#pragma unroll
        for (int q = 0; q < 4; q++) split_q(p[4 * j + q], inv2, h[q], l[q]);
        int o = 4 * (t + 256 * j);
        *reinterpret_cast<uint32_t*>(ph + o) = *reinterpret_cast<const uint32_t*>(h);
        *reinterpret_cast<uint32_t*>(pl + o) = *reinterpret_cast<const uint32_t*>(l);
    }
}

// ================= pipelined int8-split WMMA NT GEMM =================
// C = sA*sB*(65536*hh + 256*mid); hh=Ah*Bh, mid=Ah*Bl+Al*Bh (int32, exact).
// Block tile 128x128x128(int8); 256 threads; 8 warps of 32x64 tiles; 3-stage cp.async.
// MODE 0: scores f32 (scalar scales slotA,slotB).
// MODE 1: attn f32 + absmax->g_scales[4] (per-row A scale g_rowscale, scalar slotB).
// MODE 2: f32 + bias (scalar scales).
constexpr int BM = 128, BN = 128, BK = 128;
constexpr int PITCH = 144;                      // BK + 16 pad (int8)
constexpr int PLANEB = BM * PITCH;              // 18432 B per plane
constexpr int STAGEB = 4 * PLANEB;              // 73728 B
constexpr int STAGES = 3;
constexpr unsigned GSMEM = STAGES * STAGEB;     // 221184 B

template <int MODE>
__global__ void __launch_bounds__(256) gemm_i8(
    const char* __restrict__ Ah, const char* __restrict__ Al, int lda, size_t strA,
    const char* __restrict__ Bh, const char* __restrict__ Bl, int ldb, size_t strB,
    float* __restrict__ C, int ldc, size_t strC,
    const float* __restrict__ bias, int slotA, int slotB, int Kdim) {
    extern __shared__ char smem[];
    const uint32_t sbase = smem_u32(smem);
    const int tid = threadIdx.x;
    const int lane = tid & 31, wid = tid >> 5;
    const int wm = wid >> 1;                 // 0..3  (32-row strips)
    const int wn = wid & 1;                  // 0..1  (64-col strips)
    const int b = blockIdx.z;
    const int m0 = blockIdx.y * BM, n0 = blockIdx.x * BN;

    const char* pa[2] = {Ah + (size_t)b * strA, Al + (size_t)b * strA};
    const char* pb[2] = {Bh + (size_t)b * strB, Bl + (size_t)b * strB};

    const int niter = Kdim / BK;

    auto load_stage = [&](int j) {
        const int k0 = j * BK;
        const uint32_t sb = sbase + (j % STAGES) * STAGEB;
#pragma unroll
        for (int p = 0; p < 4; p++) {
            const char* src = (p < 2) ? pa[p] : pb[p - 2];
            const int r0 = (p < 2) ? m0 : n0;
            const int ld = (p < 2) ? lda : ldb;
#pragma unroll
            for (int it = 0; it < 4; it++) {
                int id = tid + it * 256;          // 1024 chunks per plane
                int r = id >> 3, c = id & 7;      // 128 rows x 8 x 16B
                uint32_t dst = sb + (uint32_t)p * PLANEB + (uint32_t)(r * PITCH + c * 16);
                cp16(dst, src + (size_t)(r0 + r) * ld + k0 + c * 16);
            }
        }
    };

    wmma::fragment<wmma::accumulator, 16, 16, 16, int> hh[2][4], md[2][4];
#pragma unroll
    for (int i = 0; i < 2; i++)
#pragma unroll
        for (int j = 0; j < 4; j++) {
            wmma::fill_fragment(hh[i][j], 0);
            wmma::fill_fragment(md[i][j], 0);
        }

    load_stage(0); cp_commit();
    load_stage(1); cp_commit();

    for (int i = 0; i < niter; i++) {
        cp_wait1();
        __syncthreads();
        if (i + 2 < niter) load_stage(i + 2);
        cp_commit();

        const char* As_hi = smem + (size_t)(i % STAGES) * STAGEB;
        const char* As_lo = As_hi + PLANEB;
        const char* Bs_hi = As_hi + 2 * PLANEB;
        const char* Bs_lo = As_hi + 3 * PLANEB;

#pragma unroll
        for (int kk = 0; kk < BK; kk += 16) {
            wmma::fragment<wmma::matrix_a, 16, 16, 16, signed char, wmma::row_major> ah[2], al[2];
#pragma unroll
            for (int x = 0; x < 2; x++) {
                int row = wm * 32 + x * 16;
                wmma::load_matrix_sync(ah[x], (const signed char*)(As_hi + row * PITCH + kk), PITCH);
                wmma::load_matrix_sync(al[x], (const signed char*)(As_lo + row * PITCH + kk), PITCH);
            }
            wmma::fragment<wmma::matrix_b, 16, 16, 16, signed char, wmma::col_major> bh[4], bl[4];
#pragma unroll
            for (int y = 0; y < 4; y++) {
                int col = wn * 64 + y * 16;
                wmma::load_matrix_sync(bh[y], (const signed char*)(Bs_hi + col * PITCH + kk), PITCH);
                wmma::load_matrix_sync(bl[y], (const signed char*)(Bs_lo + col * PITCH + kk), PITCH);
            }
#pragma unroll
            for (int x = 0; x < 2; x++)
#pragma unroll
                for (int y = 0; y < 4; y++) {
                    wmma::mma_sync(hh[x][y], ah[x], bh[y], hh[x][y]);
                    wmma::mma_sync(md[x][y], ah[x], bl[y], md[x][y]);
                    wmma::mma_sync(md[x][y], al[x], bh[y], md[x][y]);
                }
        }
        __syncthreads();
    }

    // ---------------- epilogue ----------------
    const float INVQ = 1.0f / QMAX;
    if (MODE == 0) {
        float ss = (g_scales[slotA] * INVQ) * (g_scales[slotB] * INVQ);
        float* Cb = C + (size_t)b * strC;
#pragma unroll
        for (int x = 0; x < 2; x++)
#pragma unroll
            for (int y = 0; y < 4; y++) {
                wmma::fragment<wmma::accumulator, 16, 16, 16, float> f;
#pragma unroll
                for (int e = 0; e < f.num_elements; e++)
                    f.x[e] = ss * (65536.f * (float)hh[x][y].x[e] + 256.f * (float)md[x][y].x[e]);
                int gr = m0 + wm * 32 + x * 16;
                int gc = n0 + wn * 64 + y * 16;
                wmma::store_matrix_sync(Cb + (size_t)gr * ldc + gc, f, ldc, wmma::mem_row_major);
            }
    } else {
        // stage combined (unscaled) values through smem, scale on output
        float* stage = reinterpret_cast<float*>(smem) + wid * (32 * 72);
#pragma unroll
        for (int x = 0; x < 2; x++)
#pragma unroll
            for (int y = 0; y < 4; y++) {
                wmma::fragment<wmma::accumulator, 16, 16, 16, float> f;
#pragma unroll
                for (int e = 0; e < f.num_elements; e++)
                    f.x[e] = 65536.f * (float)hh[x][y].x[e] + 256.f * (float)md[x][y].x[e];
                wmma::store_matrix_sync(stage + x * 16 * 72 + y * 16, f, 72, wmma::mem_row_major);
            }
        __syncwarp();
        int wr0 = m0 + wm * 32, wc0 = n0 + wn * 64;
        float sb = g_scales[slotB] * INVQ;
        float am = 0.f;
#pragma unroll
        for (int it = 0; it < 16; it++) {
            int idx = lane + it * 32;
            int r = idx >> 4, c = (idx & 15) << 2;
            float4 v = *reinterpret_cast<float4*>(stage + r * 72 + c);
            int gr = wr0 + r, gc = wc0 + c;
            if (MODE == 1) {
                float sa = g_rowscale[(size_t)b * S_ + gr];   // true step, no INVQ
                float f = sa * sb;
                v.x *= f; v.y *= f; v.z *= f; v.w *= f;
                am = fmaxf(am, fmaxf(fmaxf(fabsf(v.x), fabsf(v.y)),
                                     fmaxf(fabsf(v.z), fabsf(v.w))));
                float* Cb = C + (size_t)b * strC;
                *reinterpret_cast<float4*>(Cb + (size_t)gr * ldc + gc) = v;
            } else {  // MODE 2
                float ss = (g_scales[slotA] * INVQ) * sb;
                v.x = ss * v.x + bias[gc];
                v.y = ss * v.y + bias[gc + 1];
                v.z = ss * v.z + bias[gc + 2];
                v.w = ss * v.w + bias[gc + 3];
                *reinterpret_cast<float4*>(C + (size_t)gr * ldc + gc) = v;
            }
        }
        if (MODE == 1) {
#pragma unroll
            for (int o = 16; o; o >>= 1) am = fmaxf(am, __shfl_xor_sync(0xffffffffu, am, o));
            if (lane == 0)
                atomicMax(reinterpret_cast<int*>(&g_scales[4]), __float_as_int(am));
        }
    }
}

// ================= launch =================
extern "C" void kernel_launch(void* const* d_in, const int* in_sizes, int n_in,
                              void* d_out, int out_size) {
    const float* Q    = (const float*)d_in[0];
    const float* Kx   = (const float*)d_in[1];
    const float* V    = (const float*)d_in[2];
    const float* mask = (const float*)d_in[3];
    const float* W    = (const float*)d_in[4];
    const float* bias = (const float*)d_in[5];
    const int*   inv  = (const int*)d_in[6];

    void *pQh, *pQl, *pKh, *pKl, *pVh, *pVl, *pWh, *pWl, *pS, *pPh, *pPl;
    cudaGetSymbolAddress(&pQh, c_Qhi);  cudaGetSymbolAddress(&pQl, c_Qlo);
    cudaGetSymbolAddress(&pKh, c_Khi);  cudaGetSymbolAddress(&pKl, c_Klo);
    cudaGetSymbolAddress(&pVh, c_Vthi); cudaGetSymbolAddress(&pVl, c_Vtlo);
    cudaGetSymbolAddress(&pWh, c_Whi);  cudaGetSymbolAddress(&pWl, c_Wlo);
    cudaGetSymbolAddress(&pS, g_scores);
    cudaGetSymbolAddress(&pPh, c_Phi);  cudaGetSymbolAddress(&pPl, c_Plo);

    char *Qh = (char*)pQh, *Ql = (char*)pQl;
    char *Kh = (char*)pKh, *Kl = (char*)pKl;
    char *Vh = (char*)pVh, *Vl = (char*)pVl;
    char *Wh = (char*)pWh, *Wl = (char*)pWl;
    float* Sc = (float*)pS;                 // scores f32, later attn f32
    char *Ph = (char*)pPh, *Pl = (char*)pPl;

    cudaFuncSetAttribute(gemm_i8<0>, cudaFuncAttributeMaxDynamicSharedMemorySize, GSMEM);
    cudaFuncSetAttribute(gemm_i8<1>, cudaFuncAttributeMaxDynamicSharedMemorySize, GSMEM);
    cudaFuncSetAttribute(gemm_i8<2>, cudaFuncAttributeMaxDynamicSharedMemorySize, GSMEM);

    const int nQ = B_ * S_ * E_;
    const int nW = E_ * E_;

    // scales (re-zeroed every call: deterministic under graph replay)
    zero_scales_kernel<<<1, 32>>>();
    absmax_kernel<<<1024, 256>>>((const float4*)Q,  nQ / 4, 0);
    absmax_kernel<<<1024, 256>>>((const float4*)Kx, nQ / 4, 1);
    absmax_kernel<<<1024, 256>>>((const float4*)V,  nQ / 4, 2);
    absmax_kernel<<<256, 256>>>((const float4*)W,  nW / 4, 3);

    // quantize
    quant_plane<<<nQ / 8 / 256, 256>>>(Q,  Qh, Ql, nQ / 8, 0);
    quant_plane<<<nQ / 8 / 256, 256>>>(Kx, Kh, Kl, nQ / 8, 1);
    quant_plane<<<nW / 8 / 256, 256>>>(W,  Wh, Wl, nW / 8, 3);
    dim3 gt(S_ / 32, E_ / 32, B_);
    quantT_v<<<gt, 256>>>(V, Vh, Vl);

    // GEMM1: scores = Q @ K^T  [M=S, N=S, K=E]
    dim3 g1(S_ / BN, S_ / BM, B_);
    gemm_i8<0><<<g1, 256, GSMEM>>>(Qh, Ql, E_, (size_t)S_ * E_,
                                   Kh, Kl, E_, (size_t)S_ * E_,
                                   Sc, S_, (size_t)S_ * S_, nullptr, 0, 1, E_);

    // softmax * mask -> int8 P planes + per-row scales
    softmax_quant_kernel<<<B_ * S_, 256>>>(Sc, mask, Ph, Pl, inv);

    // GEMM2: attn = P @ Vt^T  [M=S, N=E, K=S]; writes f32 attn into Sc + absmax slot 4
    dim3 g2(E_ / BN, S_ / BM, B_);
    gemm_i8<1><<<g2, 256, GSMEM>>>(Ph, Pl, S_, (size_t)S_ * S_,
                                   Vh, Vl, S_, (size_t)E_ * S_,
                                   Sc, E_, (size_t)S_ * E_, nullptr, 0, 2, S_);

    // quantize attn (reuse Q planes)
    quant_plane<<<nQ / 8 / 256, 256>>>(Sc, Qh, Ql, nQ / 8, 4);

    // GEMM3: out = attn @ W^T + bias  [M=B*S, N=E, K=E]
    dim3 g3(E_ / BN, (B_ * S_) / BM, 1);
    gemm_i8<2><<<g3, 256, GSMEM>>>(Qh, Ql, E_, 0,
                                   Wh, Wl, E_, 0,
                                   (float*)d_out, E_, 0, bias, 4, 3, E_);
}

// round 10
// speedup vs baseline: 2.8350x; 2.8350x over previous
#include <cuda_runtime.h>
#include <cuda_bf16.h>
#include <cstdint>
#include <cstddef>
#include <mma.h>

using namespace nvcuda;

#define B_ 8
#define S_ 2048
#define E_ 1024

// ================= scratch (device globals; allocation-free rule) =================
__device__ float g_Qc[(size_t)B_ * S_ * E_];   // tf32-rounded copies
__device__ float g_Kc[(size_t)B_ * S_ * E_];
__device__ float g_Vt[(size_t)B_ * E_ * S_];   // V transposed [B,E,S], tf32-rounded
__device__ float g_Wc[(size_t)E_ * E_];
__device__ float g_scores[(size_t)B_ * S_ * S_]; // scores f32 -> probs (in place)
__device__ float g_attn[(size_t)B_ * S_ * E_];

// ================= helpers =================
__device__ __forceinline__ uint32_t smem_u32(const void* p) {
    uint32_t a;
    asm("{ .reg .u64 t; cvta.to.shared.u64 t, %1; cvt.u32.u64 %0, t; }" : "=r"(a) : "l"(p));
    return a;
}
__device__ __forceinline__ void cp16(uint32_t dst, const void* src) {
    asm volatile("cp.async.cg.shared.global [%0], [%1], 16;" :: "r"(dst), "l"(src) : "memory");
}
__device__ __forceinline__ void cp_commit() { asm volatile("cp.async.commit_group;" ::: "memory"); }
__device__ __forceinline__ void cp_wait1()  { asm volatile("cp.async.wait_group 1;" ::: "memory"); }
__device__ __forceinline__ float to_tf32(float x) {
    float y;
    asm("cvt.rna.tf32.f32 %0, %1;" : "=f"(y) : "f"(x));
    return y;
}

// ================= prep kernels =================
// f32 -> tf32-rounded f32 copy (round-to-nearest, low mantissa bits zeroed)
__global__ void __launch_bounds__(256) cvt_copy(const float4* __restrict__ x,
                                                float4* __restrict__ y, int n4) {
    int i = blockIdx.x * blockDim.x + threadIdx.x;
    if (i >= n4) return;
    float4 v = x[i];
    v.x = to_tf32(v.x); v.y = to_tf32(v.y);
    v.z = to_tf32(v.z); v.w = to_tf32(v.w);
    y[i] = v;
}

// V [B,S,E] -> [B,E,S] with tf32 rounding
__global__ void __launch_bounds__(256) transpose_v(const float* __restrict__ v,
                                                   float* __restrict__ vt) {
    __shared__ float tile[32][33];
    int b = blockIdx.z;
    int s0 = blockIdx.x * 32, e0 = blockIdx.y * 32;
    int tx = threadIdx.x & 31, ty = threadIdx.x >> 5;
    const float* vb = v + (size_t)b * S_ * E_;
#pragma unroll
    for (int k = 0; k < 4; k++)
        tile[ty + 8 * k][tx] = vb[(size_t)(s0 + ty + 8 * k) * E_ + e0 + tx];
    __syncthreads();
    float* ob = vt + (size_t)b * E_ * S_;
#pragma unroll
    for (int k = 0; k < 4; k++)
        ob[(size_t)(e0 + ty + 8 * k) * S_ + s0 + tx] = to_tf32(tile[tx][ty + 8 * k]);
}

// ================= softmax * mask, in place, tf32-rounded output =================
__global__ void __launch_bounds__(256) softmax_mask_kernel(
    float* __restrict__ scores, const float* __restrict__ mask,
    const int* __restrict__ sc) {
    __shared__ float redmax[8], redsum[8];
    size_t row = blockIdx.x;
    float4* srow = reinterpret_cast<float4*>(scores + row * (size_t)S_);
    const float4* mrow = reinterpret_cast<const float4*>(mask + row * (size_t)S_);
    int t = threadIdx.x, lane = t & 31, warp = t >> 5;

    int iv = *sc;
    float denom = (iv == 32) ? 32.0f : __int_as_float(iv);
    float scale = 1.0f / denom;

    float v[8];
#pragma unroll
    for (int j = 0; j < 2; j++) {
        float4 x = srow[t + 256 * j];
        v[4 * j + 0] = x.x * scale; v[4 * j + 1] = x.y * scale;
        v[4 * j + 2] = x.z * scale; v[4 * j + 3] = x.w * scale;
    }
    float m = v[0];
#pragma unroll
    for (int j = 1; j < 8; j++) m = fmaxf(m, v[j]);
#pragma unroll
    for (int o = 16; o; o >>= 1) m = fmaxf(m, __shfl_xor_sync(0xffffffffu, m, o));
    if (lane == 0) redmax[warp] = m;
    __syncthreads();
    float bm = redmax[0];
#pragma unroll
    for (int w = 1; w < 8; w++) bm = fmaxf(bm, redmax[w]);
    float e[8], s = 0.f;
#pragma unroll
    for (int j = 0; j < 8; j++) { e[j] = __expf(v[j] - bm); s += e[j]; }
#pragma unroll
    for (int o = 16; o; o >>= 1) s += __shfl_xor_sync(0xffffffffu, s, o);
    if (lane == 0) redsum[warp] = s;
    __syncthreads();
    float bs = 0.f;
#pragma unroll
    for (int w = 0; w < 8; w++) bs += redsum[w];
    float inv = 1.0f / bs;

#pragma unroll
    for (int j = 0; j < 2; j++) {
        float4 mk = mrow[t + 256 * j];
        float4 o;
        o.x = to_tf32(e[4 * j + 0] * inv * mk.x);
        o.y = to_tf32(e[4 * j + 1] * inv * mk.y);
        o.z = to_tf32(e[4 * j + 2] * inv * mk.z);
        o.w = to_tf32(e[4 * j + 3] * inv * mk.w);
        srow[t + 256 * j] = o;
    }
}

// ================= pipelined tf32 WMMA NT GEMM =================
// C[M,N] = sum_k A[m,k]*B[n,k]; A/B tf32-rounded f32; fp32 accum (m16n16k8).
// Block 128x128x64; 256 threads; 8 warps of 32x64 tiles; 3-stage cp.async.
// MODE 0: f32 out. MODE 1: tf32-rounded f32 out. MODE 2: f32 + bias out.
constexpr int BM = 128, BN = 128, BK = 64;
constexpr int PITCH = 68;                       // BK + 4 pad (f32) = 272 B/row
constexpr int PLANEB = BM * PITCH * 4;          // 34816 B per tile
constexpr int STAGEB = 2 * PLANEB;              // A + B = 69632 B
constexpr int STAGES = 3;
constexpr unsigned GSMEM = STAGES * STAGEB;     // 208896 B

template <int MODE>
__global__ void __launch_bounds__(256) gemm_tf32(
    const float* __restrict__ A, int lda, size_t strA,
    const float* __restrict__ Bm, int ldb, size_t strB,
    float* __restrict__ C, int ldc, size_t strC,
    const float* __restrict__ bias, int Kdim) {
    extern __shared__ float smem[];
    const uint32_t sbase = smem_u32(smem);
    const int tid = threadIdx.x;
    const int lane = tid & 31, wid = tid >> 5;
    const int wm = wid >> 1;                 // 0..3  (32-row strips)
    const int wn = wid & 1;                  // 0..1  (64-col strips)
    const int b = blockIdx.z;
    const int m0 = blockIdx.y * BM, n0 = blockIdx.x * BN;

    const float* Ab = A + (size_t)b * strA;
    const float* Bb = Bm + (size_t)b * strB;

    const int niter = Kdim / BK;

    // stage loader: A,B tiles 128 x 64 f32; 16B chunks (16/row)
    auto load_stage = [&](int j) {
        const int k0 = j * BK;
        const uint32_t sb = sbase + (j % STAGES) * STAGEB;
#pragma unroll
        for (int it = 0; it < 8; it++) {
            int id = tid + it * 256;             // 2048 chunks
            int r = id >> 4, c = id & 15;        // 128 rows x 16 chunks
            uint32_t dst = sb + (uint32_t)(r * (PITCH * 4) + c * 16);
            cp16(dst, Ab + (size_t)(m0 + r) * lda + k0 + c * 4);
        }
#pragma unroll
        for (int it = 0; it < 8; it++) {
            int id = tid + it * 256;
            int r = id >> 4, c = id & 15;
            uint32_t dst = sb + (uint32_t)PLANEB + (uint32_t)(r * (PITCH * 4) + c * 16);
            cp16(dst, Bb + (size_t)(n0 + r) * ldb + k0 + c * 4);
        }
    };

    wmma::fragment<wmma::accumulator, 16, 16, 8, float> acc[2][4];
#pragma unroll
    for (int i = 0; i < 2; i++)
#pragma unroll
        for (int j = 0; j < 4; j++) wmma::fill_fragment(acc[i][j], 0.f);

    load_stage(0); cp_commit();
    load_stage(1); cp_commit();

    for (int i = 0; i < niter; i++) {
        cp_wait1();
        __syncthreads();
        if (i + 2 < niter) load_stage(i + 2);
        cp_commit();

        const float* As = smem + (size_t)(i % STAGES) * (STAGEB / 4);
        const float* Bs = As + PLANEB / 4;

#pragma unroll
        for (int kk = 0; kk < BK; kk += 8) {
            wmma::fragment<wmma::matrix_a, 16, 16, 8, wmma::precision::tf32,
                           wmma::row_major> af[2];
#pragma unroll
            for (int x = 0; x < 2; x++) {
                int row = wm * 32 + x * 16;
                wmma::load_matrix_sync(af[x], As + row * PITCH + kk, PITCH);
            }
            wmma::fragment<wmma::matrix_b, 16, 16, 8, wmma::precision::tf32,
                           wmma::col_major> bf[4];
#pragma unroll
            for (int y = 0; y < 4; y++) {
                int col = wn * 64 + y * 16;
                wmma::load_matrix_sync(bf[y], Bs + col * PITCH + kk, PITCH);
            }
#pragma unroll
            for (int x = 0; x < 2; x++)
#pragma unroll
                for (int y = 0; y < 4; y++)
                    wmma::mma_sync(acc[x][y], af[x], bf[y], acc[x][y]);
        }
        __syncthreads();
    }

    // ---------------- epilogue ----------------
    if (MODE == 0) {
        float* Cb = C + (size_t)b * strC;
#pragma unroll
        for (int x = 0; x < 2; x++)
#pragma unroll
            for (int y = 0; y < 4; y++) {
                int gr = m0 + wm * 32 + x * 16;
                int gc = n0 + wn * 64 + y * 16;
                wmma::store_matrix_sync(Cb + (size_t)gr * ldc + gc, acc[x][y], ldc,
                                        wmma::mem_row_major);
            }
    } else {
        // stage through smem for vectorized writes (stage buffers dead)
        float* stage = smem + wid * (32 * 72);
#pragma unroll
        for (int x = 0; x < 2; x++)
#pragma unroll
            for (int y = 0; y < 4; y++)
                wmma::store_matrix_sync(stage + x * 16 * 72 + y * 16, acc[x][y], 72,
                                        wmma::mem_row_major);
        __syncwarp();
        int wr0 = m0 + wm * 32, wc0 = n0 + wn * 64;
#pragma unroll
        for (int it = 0; it < 16; it++) {
            int idx = lane + it * 32;
            int r = idx >> 4, c = (idx & 15) << 2;
            float4 v = *reinterpret_cast<float4*>(stage + r * 72 + c);
            int gr = wr0 + r, gc = wc0 + c;
            if (MODE == 2) {
                v.x += bias[gc]; v.y += bias[gc + 1];
                v.z += bias[gc + 2]; v.w += bias[gc + 3];
                *reinterpret_cast<float4*>(C + (size_t)gr * ldc + gc) = v;
            } else {  // MODE 1: tf32-rounded f32 (feeds next tf32 GEMM)
                v.x = to_tf32(v.x); v.y = to_tf32(v.y);
                v.z = to_tf32(v.z); v.w = to_tf32(v.w);
                float* Cb = C + (size_t)b * strC;
                *reinterpret_cast<float4*>(Cb + (size_t)gr * ldc + gc) = v;
            }
        }
    }
}

// ================= launch =================
extern "C" void kernel_launch(void* const* d_in, const int* in_sizes, int n_in,
                              void* d_out, int out_size) {
    const float* Q    = (const float*)d_in[0];
    const float* Kx   = (const float*)d_in[1];
    const float* V    = (const float*)d_in[2];
    const float* mask = (const float*)d_in[3];
    const float* W    = (const float*)d_in[4];
    const float* bias = (const float*)d_in[5];
    const int*   inv  = (const int*)d_in[6];

    void *pQ, *pK, *pVt, *pW, *pS, *pA;
    cudaGetSymbolAddress(&pQ, g_Qc);
    cudaGetSymbolAddress(&pK, g_Kc);
    cudaGetSymbolAddress(&pVt, g_Vt);
    cudaGetSymbolAddress(&pW, g_Wc);
    cudaGetSymbolAddress(&pS, g_scores);
    cudaGetSymbolAddress(&pA, g_attn);

    float *Qc = (float*)pQ, *Kc = (float*)pK, *Vt = (float*)pVt, *Wc = (float*)pW;
    float *Sc = (float*)pS, *At = (float*)pA;

    cudaFuncSetAttribute(gemm_tf32<0>, cudaFuncAttributeMaxDynamicSharedMemorySize, GSMEM);
    cudaFuncSetAttribute(gemm_tf32<1>, cudaFuncAttributeMaxDynamicSharedMemorySize, GSMEM);
    cudaFuncSetAttribute(gemm_tf32<2>, cudaFuncAttributeMaxDynamicSharedMemorySize, GSMEM);

    const int nQ4 = B_ * S_ * E_ / 4;
    const int nW4 = E_ * E_ / 4;

    // prep: tf32-rounded copies (no splits at all)
    cvt_copy<<<nQ4 / 256, 256>>>((const float4*)Q,  (float4*)Qc, nQ4);
    cvt_copy<<<nQ4 / 256, 256>>>((const float4*)Kx, (float4*)Kc, nQ4);
    cvt_copy<<<nW4 / 256, 256>>>((const float4*)W,  (float4*)Wc, nW4);
    dim3 gt(S_ / 32, E_ / 32, B_);
    transpose_v<<<gt, 256>>>(V, Vt);

    // GEMM1: scores = Q @ K^T  [M=S, N=S, K=E]
    dim3 g1(S_ / BN, S_ / BM, B_);
    gemm_tf32<0><<<g1, 256, GSMEM>>>(Qc, E_, (size_t)S_ * E_,
                                     Kc, E_, (size_t)S_ * E_,
                                     Sc, S_, (size_t)S_ * S_, nullptr, E_);

    // softmax * mask, in place (tf32-rounded probs)
    softmax_mask_kernel<<<B_ * S_, 256>>>(Sc, mask, inv);

    // GEMM2: attn = P @ Vt^T  [M=S, N=E, K=S]  (MODE 1: tf32-rounded attn)
    dim3 g2(E_ / BN, S_ / BM, B_);
    gemm_tf32<1><<<g2, 256, GSMEM>>>(Sc, S_, (size_t)S_ * S_,
                                     Vt, S_, (size_t)E_ * S_,
                                     At, E_, (size_t)S_ * E_, nullptr, S_);

    // GEMM3: out = attn @ W^T + bias  [M=B*S, N=E, K=E]
    dim3 g3(E_ / BN, (B_ * S_) / BM, 1);
    gemm_tf32<2><<<g3, 256, GSMEM>>>(At, E_, 0,
                                     Wc, E_, 0,
                                     (float*)d_out, E_, 0, bias, E_);
}

// round 11
// speedup vs baseline: 4.5067x; 1.5897x over previous
#include <cuda_runtime.h>
#include <cuda_bf16.h>
#include <cstdint>
#include <cstddef>
#include <mma.h>

using namespace nvcuda;

#define B_ 8
#define S_ 2048
#define E_ 1024

// ================= scratch (device globals; allocation-free rule) =================
__device__ __nv_bfloat16 g_Qhi[(size_t)B_ * S_ * E_];
__device__ __nv_bfloat16 g_Qlo[(size_t)B_ * S_ * E_];
__device__ __nv_bfloat16 g_Khi[(size_t)B_ * S_ * E_];
__device__ __nv_bfloat16 g_Klo[(size_t)B_ * S_ * E_];
__device__ __nv_bfloat16 g_Vthi[(size_t)B_ * E_ * S_];  // V transposed: [B, E, S]
__device__ __nv_bfloat16 g_Vtlo[(size_t)B_ * E_ * S_];
__device__ __nv_bfloat16 g_Whi[(size_t)E_ * E_];
__device__ __nv_bfloat16 g_Wlo[(size_t)E_ * E_];
__device__ float         g_scores[(size_t)B_ * S_ * S_];
__device__ __nv_bfloat16 g_Phi[(size_t)B_ * S_ * S_];
__device__ __nv_bfloat16 g_Plo[(size_t)B_ * S_ * S_];
// attn split reuses g_Qhi/g_Qlo (Q dead after GEMM1)

// ================= async-copy helpers =================
__device__ __forceinline__ uint32_t smem_u32(const void* p) {
    uint32_t a;
    asm("{ .reg .u64 t; cvta.to.shared.u64 t, %1; cvt.u32.u64 %0, t; }" : "=r"(a) : "l"(p));
    return a;
}
__device__ __forceinline__ void cp16(uint32_t dst, const void* src) {
    asm volatile("cp.async.cg.shared.global [%0], [%1], 16;" :: "r"(dst), "l"(src) : "memory");
}
__device__ __forceinline__ void cp_commit() { asm volatile("cp.async.commit_group;" ::: "memory"); }
__device__ __forceinline__ void cp_wait1()  { asm volatile("cp.async.wait_group 1;" ::: "memory"); }

// ================= split kernels =================
__global__ void __launch_bounds__(256) split_plane(const float* __restrict__ x,
                                                   __nv_bfloat16* __restrict__ hi,
                                                   __nv_bfloat16* __restrict__ lo, int n8) {
    int i = blockIdx.x * blockDim.x + threadIdx.x;
    if (i >= n8) return;
    const float4* x4 = reinterpret_cast<const float4*>(x) + (size_t)i * 2;
    float4 a = x4[0], b = x4[1];
    float f[8] = {a.x, a.y, a.z, a.w, b.x, b.y, b.z, b.w};
    __nv_bfloat16 h[8], l[8];
#pragma unroll
    for (int j = 0; j < 8; j++) {
        h[j] = __float2bfloat16(f[j]);
        l[j] = __float2bfloat16(f[j] - __bfloat162float(h[j]));
    }
    *reinterpret_cast<uint4*>(hi + (size_t)i * 8) = *reinterpret_cast<const uint4*>(h);
    *reinterpret_cast<uint4*>(lo + (size_t)i * 8) = *reinterpret_cast<const uint4*>(l);
}

// V [B,S,E] f32 -> transposed planes [B,E,S] bf16 hi/lo
__global__ void __launch_bounds__(256) splitT_v(const float* __restrict__ v,
                                                __nv_bfloat16* __restrict__ hi,
                                                __nv_bfloat16* __restrict__ lo) {
    __shared__ float tile[32][33];
    int b = blockIdx.z;
    int s0 = blockIdx.x * 32, e0 = blockIdx.y * 32;
    int tx = threadIdx.x & 31, ty = threadIdx.x >> 5;
    const float* vb = v + (size_t)b * S_ * E_;
#pragma unroll
    for (int k = 0; k < 4; k++)
        tile[ty + 8 * k][tx] = vb[(size_t)(s0 + ty + 8 * k) * E_ + e0 + tx];
    __syncthreads();
    __nv_bfloat16* hb = hi + (size_t)b * E_ * S_;
    __nv_bfloat16* lb = lo + (size_t)b * E_ * S_;
#pragma unroll
    for (int k = 0; k < 4; k++) {
        float f = tile[tx][ty + 8 * k];
        __nv_bfloat16 h = __float2bfloat16(f);
        size_t o = (size_t)(e0 + ty + 8 * k) * S_ + s0 + tx;
        hb[o] = h;
        lb[o] = __float2bfloat16(f - __bfloat162float(h));
    }
}

// ================= softmax * mask -> planar bf16 hi/lo probs (vectorized) ========
__global__ void __launch_bounds__(256) softmax_mask_kernel(
    const float* __restrict__ scores, const float* __restrict__ mask,
    __nv_bfloat16* __restrict__ phi, __nv_bfloat16* __restrict__ plo,
    const int* __restrict__ sc) {
    __shared__ float redmax[8], redsum[8];
    size_t row = blockIdx.x;
    const float4* srow = reinterpret_cast<const float4*>(scores + row * (size_t)S_);
    const float4* mrow = reinterpret_cast<const float4*>(mask + row * (size_t)S_);
    int t = threadIdx.x, lane = t & 31, warp = t >> 5;

    int iv = *sc;
    float denom = (iv == 32) ? 32.0f : __int_as_float(iv);
    float scale = 1.0f / denom;

    float v[8];
#pragma unroll
    for (int j = 0; j < 2; j++) {
        float4 x = srow[t + 256 * j];
        v[4 * j + 0] = x.x * scale; v[4 * j + 1] = x.y * scale;
        v[4 * j + 2] = x.z * scale; v[4 * j + 3] = x.w * scale;
    }
    float m = v[0];
#pragma unroll
    for (int j = 1; j < 8; j++) m = fmaxf(m, v[j]);
#pragma unroll
    for (int o = 16; o; o >>= 1) m = fmaxf(m, __shfl_xor_sync(0xffffffffu, m, o));
    if (lane == 0) redmax[warp] = m;
    __syncthreads();
    float bm = redmax[0];
#pragma unroll
    for (int w = 1; w < 8; w++) bm = fmaxf(bm, redmax[w]);
    float e[8], s = 0.f;
#pragma unroll
    for (int j = 0; j < 8; j++) { e[j] = __expf(v[j] - bm); s += e[j]; }
#pragma unroll
    for (int o = 16; o; o >>= 1) s += __shfl_xor_sync(0xffffffffu, s, o);
    if (lane == 0) redsum[warp] = s;
    __syncthreads();
    float bs = 0.f;
#pragma unroll
    for (int w = 0; w < 8; w++) bs += redsum[w];
    float inv = 1.0f / bs;

    __nv_bfloat16* ph = phi + row * (size_t)S_;
    __nv_bfloat16* pl = plo + row * (size_t)S_;
#pragma unroll
    for (int j = 0; j < 2; j++) {
        float4 mk = mrow[t + 256 * j];
        float mf[4] = {mk.x, mk.y, mk.z, mk.w};
        __nv_bfloat16 h[4], l[4];
#pragma unroll
        for (int q = 0; q < 4; q++) {
            float p = e[4 * j + q] * inv * mf[q];
            h[q] = __float2bfloat16(p);
            l[q] = __float2bfloat16(p - __bfloat162float(h[q]));
        }
        int o = 4 * (t + 256 * j);
        *reinterpret_cast<uint2*>(ph + o) = *reinterpret_cast<const uint2*>(h);
        *reinterpret_cast<uint2*>(pl + o) = *reinterpret_cast<const uint2*>(l);
    }
}

// ================= pipelined split-bf16 WMMA NT GEMM (reg double-buffered) =======
// C[M,N] = sum_k A[m,k]*B[n,k]; A/B planar hi/lo bf16, fp32 accum via HMMA.
// MODE 0: f32 out. MODE 1: planar bf16 hi/lo out. MODE 2: f32 + bias out.
constexpr int BM = 128, BN = 128, BK = 64;
constexpr int PITCH = 72;                       // BK + 8 pad (bf16 elems)
constexpr int PLANEB = BM * PITCH * 2;          // 18432 B per plane tile
constexpr int STAGEB = 4 * PLANEB;              // Ahi/Alo/Bhi/Blo = 73728 B
constexpr int STAGES = 3;
constexpr unsigned GSMEM = STAGES * STAGEB;     // 221184 B

template <int MODE>
__global__ void __launch_bounds__(256) gemm_pipe(
    const __nv_bfloat16* __restrict__ Ahi, const __nv_bfloat16* __restrict__ Alo,
    int lda, size_t strA,
    const __nv_bfloat16* __restrict__ Bhi, const __nv_bfloat16* __restrict__ Blo,
    int ldb, size_t strB,
    void* __restrict__ C0, void* __restrict__ C1, int ldc, size_t strC,
    const float* __restrict__ bias, int Kdim) {
    extern __shared__ __nv_bfloat16 smem[];
    const uint32_t sbase = smem_u32(smem);
    const int tid = threadIdx.x;
    const int lane = tid & 31, wid = tid >> 5;
    const int wm = wid >> 1;                 // 0..3  (32-row strips)
    const int wn = wid & 1;                  // 0..1  (64-col strips)
    const int b = blockIdx.z;
    const int m0 = blockIdx.y * BM, n0 = blockIdx.x * BN;

    const __nv_bfloat16* pa[2] = {Ahi + (size_t)b * strA, Alo + (size_t)b * strA};
    const __nv_bfloat16* pb[2] = {Bhi + (size_t)b * strB, Blo + (size_t)b * strB};

    const int niter = Kdim / BK;

    // stage loader: 4 planes x (128 rows x 64 bf16) with cp.async 16B chunks
    auto load_stage = [&](int j) {
        const int k0 = j * BK;
        const uint32_t sb = sbase + (j % STAGES) * STAGEB;
#pragma unroll
        for (int p = 0; p < 4; p++) {
            const __nv_bfloat16* src = (p < 2) ? pa[p] : pb[p - 2];
            const int r0 = (p < 2) ? m0 : n0;
            const int ld = (p < 2) ? lda : ldb;
#pragma unroll
            for (int it = 0; it < 4; it++) {
                int id = tid + it * 256;          // 1024 chunks
                int r = id >> 3, c = id & 7;      // 128 rows x 8 x 16B
                uint32_t dst = sb + (uint32_t)p * PLANEB + (uint32_t)(r * PITCH * 2 + c * 16);
                cp16(dst, src + (size_t)(r0 + r) * ld + k0 + c * 8);
            }
        }
    };

    wmma::fragment<wmma::accumulator, 16, 16, 16, float> acc[2][4];
#pragma unroll
    for (int i = 0; i < 2; i++)
#pragma unroll
        for (int j = 0; j < 4; j++) wmma::fill_fragment(acc[i][j], 0.f);

    // prologue
    load_stage(0); cp_commit();
    load_stage(1); cp_commit();

    for (int i = 0; i < niter; i++) {
        cp_wait1();          // stage i resident (only stage i+1 may still be in flight)
        __syncthreads();

        // prefetch stage i+2 (overwrites buffer of stage i-1; safe past the barrier)
        if (i + 2 < niter) load_stage(i + 2);
        cp_commit();

        // compute stage i
        const __nv_bfloat16* As_hi =
            smem + (size_t)(i % STAGES) * (STAGEB / 2);
        const __nv_bfloat16* As_lo = As_hi + PLANEB / 2;
        const __nv_bfloat16* Bs_hi = As_hi + 2 * (PLANEB / 2);
        const __nv_bfloat16* Bs_lo = As_hi + 3 * (PLANEB / 2);

        // register double-buffer: load k-step kk+16 fragments before kk's MMAs
        wmma::fragment<wmma::matrix_a, 16, 16, 16, __nv_bfloat16, wmma::row_major>
            ah[2][2], al[2][2];
        wmma::fragment<wmma::matrix_b, 16, 16, 16, __nv_bfloat16, wmma::col_major>
            bh[2][4], bl[2][4];

        // load kk = 0 into buffer 0
#pragma unroll
        for (int x = 0; x < 2; x++) {
            int row = wm * 32 + x * 16;
            wmma::load_matrix_sync(ah[0][x], As_hi + row * PITCH, PITCH);
            wmma::load_matrix_sync(al[0][x], As_lo + row * PITCH, PITCH);
        }
#pragma unroll
        for (int y = 0; y < 4; y++) {
            int col = wn * 64 + y * 16;
            wmma::load_matrix_sync(bh[0][y], Bs_hi + col * PITCH, PITCH);
            wmma::load_matrix_sync(bl[0][y], Bs_lo + col * PITCH, PITCH);
        }

#pragma unroll
        for (int kk = 0; kk < BK; kk += 16) {
            const int cur = (kk >> 4) & 1;
            const int nxt = cur ^ 1;
            if (kk + 16 < BK) {
                // prefetch next k-step's fragments (hides LDSM latency under MMAs)
#pragma unroll
                for (int x = 0; x < 2; x++) {
                    int row = wm * 32 + x * 16;
                    wmma::load_matrix_sync(ah[nxt][x], As_hi + row * PITCH + kk + 16, PITCH);
                    wmma::load_matrix_sync(al[nxt][x], As_lo + row * PITCH + kk + 16, PITCH);
                }
#pragma unroll
                for (int y = 0; y < 4; y++) {
                    int col = wn * 64 + y * 16;
                    wmma::load_matrix_sync(bh[nxt][y], Bs_hi + col * PITCH + kk + 16, PITCH);
                    wmma::load_matrix_sync(bl[nxt][y], Bs_lo + col * PITCH + kk + 16, PITCH);
                }
            }
            // phase-ordered issue on current buffer (per-acc order hh -> hl -> lh)
#pragma unroll
            for (int x = 0; x < 2; x++)
#pragma unroll
                for (int y = 0; y < 4; y++)
                    wmma::mma_sync(acc[x][y], ah[cur][x], bh[cur][y], acc[x][y]);
#pragma unroll
            for (int x = 0; x < 2; x++)
#pragma unroll
                for (int y = 0; y < 4; y++)
                    wmma::mma_sync(acc[x][y], ah[cur][x], bl[cur][y], acc[x][y]);
#pragma unroll
            for (int x = 0; x < 2; x++)
#pragma unroll
                for (int y = 0; y < 4; y++)
                    wmma::mma_sync(acc[x][y], al[cur][x], bh[cur][y], acc[x][y]);
        }
        __syncthreads();
    }

    // ---------------- epilogue ----------------
    if (MODE == 0) {
        float* C = reinterpret_cast<float*>(C0) + (size_t)b * strC;
#pragma unroll
        for (int x = 0; x < 2; x++)
#pragma unroll
            for (int y = 0; y < 4; y++) {
                int gr = m0 + wm * 32 + x * 16;
                int gc = n0 + wn * 64 + y * 16;
                wmma::store_matrix_sync(C + (size_t)gr * ldc + gc, acc[x][y], ldc,
                                        wmma::mem_row_major);
            }
    } else {
        // stage accumulators through smem for coalesced stores (stage buffers dead)
        float* stage = reinterpret_cast<float*>(smem) + wid * (32 * 72);
#pragma unroll
        for (int x = 0; x < 2; x++)
#pragma unroll
            for (int y = 0; y < 4; y++)
                wmma::store_matrix_sync(stage + x * 16 * 72 + y * 16, acc[x][y], 72,
                                        wmma::mem_row_major);
        __syncwarp();
        int wr0 = m0 + wm * 32, wc0 = n0 + wn * 64;
#pragma unroll
        for (int it = 0; it < 16; it++) {
            int idx = lane + it * 32;
            int r = idx >> 4, c = (idx & 15) << 2;
            float4 v = *reinterpret_cast<float4*>(stage + r * 72 + c);
            int gr = wr0 + r, gc = wc0 + c;
            if (MODE == 2) {
                v.x += bias[gc]; v.y += bias[gc + 1]; v.z += bias[gc + 2]; v.w += bias[gc + 3];
                float* C = reinterpret_cast<float*>(C0);
                *reinterpret_cast<float4*>(C + (size_t)gr * ldc + gc) = v;
            } else {
                __nv_bfloat16* Ch = reinterpret_cast<__nv_bfloat16*>(C0) + (size_t)b * strC;
                __nv_bfloat16* Cl = reinterpret_cast<__nv_bfloat16*>(C1) + (size_t)b * strC;
                float f[4] = {v.x, v.y, v.z, v.w};
                __nv_bfloat16 h[4], l[4];
#pragma unroll
                for (int q = 0; q < 4; q++) {
                    h[q] = __float2bfloat16(f[q]);
                    l[q] = __float2bfloat16(f[q] - __bfloat162float(h[q]));
                }
                size_t o = (size_t)gr * ldc + gc;
                *reinterpret_cast<uint2*>(Ch + o) = *reinterpret_cast<const uint2*>(h);
                *reinterpret_cast<uint2*>(Cl + o) = *reinterpret_cast<const uint2*>(l);
            }
        }
    }
}

// ================= launch =================
extern "C" void kernel_launch(void* const* d_in, const int* in_sizes, int n_in,
                              void* d_out, int out_size) {
    const float* Q    = (const float*)d_in[0];
    const float* Kx   = (const float*)d_in[1];
    const float* V    = (const float*)d_in[2];
    const float* mask = (const float*)d_in[3];
    const float* W    = (const float*)d_in[4];
    const float* bias = (const float*)d_in[5];
    const int*   inv  = (const int*)d_in[6];

    void *pQh, *pQl, *pKh, *pKl, *pVh, *pVl, *pWh, *pWl, *pS, *pPh, *pPl;
    cudaGetSymbolAddress(&pQh, g_Qhi);  cudaGetSymbolAddress(&pQl, g_Qlo);
    cudaGetSymbolAddress(&pKh, g_Khi);  cudaGetSymbolAddress(&pKl, g_Klo);
    cudaGetSymbolAddress(&pVh, g_Vthi); cudaGetSymbolAddress(&pVl, g_Vtlo);
    cudaGetSymbolAddress(&pWh, g_Whi);  cudaGetSymbolAddress(&pWl, g_Wlo);
    cudaGetSymbolAddress(&pS, g_scores);
    cudaGetSymbolAddress(&pPh, g_Phi);  cudaGetSymbolAddress(&pPl, g_Plo);

    __nv_bfloat16 *Qh = (__nv_bfloat16*)pQh, *Ql = (__nv_bfloat16*)pQl;
    __nv_bfloat16 *Kh = (__nv_bfloat16*)pKh, *Kl = (__nv_bfloat16*)pKl;
    __nv_bfloat16 *Vh = (__nv_bfloat16*)pVh, *Vl = (__nv_bfloat16*)pVl;
    __nv_bfloat16 *Wh = (__nv_bfloat16*)pWh, *Wl = (__nv_bfloat16*)pWl;
    float* Sc = (float*)pS;
    __nv_bfloat16 *Ph = (__nv_bfloat16*)pPh, *Pl = (__nv_bfloat16*)pPl;
    __nv_bfloat16 *Ath = Qh, *Atl = Ql;  // attn reuses Q planes

    cudaFuncSetAttribute(gemm_pipe<0>, cudaFuncAttributeMaxDynamicSharedMemorySize, GSMEM);
    cudaFuncSetAttribute(gemm_pipe<1>, cudaFuncAttributeMaxDynamicSharedMemorySize, GSMEM);
    cudaFuncSetAttribute(gemm_pipe<2>, cudaFuncAttributeMaxDynamicSharedMemorySize, GSMEM);

    const int n8 = B_ * S_ * E_ / 8;
    const int w8 = E_ * E_ / 8;

    // launch order puts GEMM1 at index 3 (the slot ncu has been capturing)
    split_plane<<<(n8 + 255) / 256, 256>>>(Q, Qh, Ql, n8);     // 0
    split_plane<<<(n8 + 255) / 256, 256>>>(Kx, Kh, Kl, n8);    // 1
    split_plane<<<(w8 + 255) / 256, 256>>>(W, Wh, Wl, w8);     // 2

    // GEMM1: scores = Q @ K^T  [M=S, N=S, K=E]                   3
    dim3 g1(S_ / BN, S_ / BM, B_);
    gemm_pipe<0><<<g1, 256, GSMEM>>>(Qh, Ql, E_, (size_t)S_ * E_,
                                     Kh, Kl, E_, (size_t)S_ * E_,
                                     Sc, nullptr, S_, (size_t)S_ * S_, nullptr, E_);

    // V split (needed only by GEMM2)                              4
    dim3 gt(S_ / 32, E_ / 32, B_);
    splitT_v<<<gt, 256>>>(V, Vh, Vl);

    // softmax * mask -> planar probs                              5
    softmax_mask_kernel<<<B_ * S_, 256>>>(Sc, mask, Ph, Pl, inv);

    // GEMM2: attn = P @ Vt^T   [M=S, N=E, K=S]                    6
    dim3 g2(E_ / BN, S_ / BM, B_);
    gemm_pipe<1><<<g2, 256, GSMEM>>>(Ph, Pl, S_, (size_t)S_ * S_,
                                     Vh, Vl, S_, (size_t)E_ * S_,
                                     Ath, Atl, E_, (size_t)S_ * E_, nullptr, S_);

    // GEMM3: out = attn @ W^T + bias  [M=B*S, N=E, K=E]           7
    dim3 g3(E_ / BN, (B_ * S_) / BM, 1);
    gemm_pipe<2><<<g3, 256, GSMEM>>>(Ath, Atl, E_, 0,
                                     Wh, Wl, E_, 0,
                                     d_out, nullptr, E_, 0, bias, E_);
}